// round 16
// baseline (speedup 1.0000x reference)
#include <cuda_runtime.h>
#include <cuda_fp16.h>
#include <cstdint>
#include <math.h>

// ---------------- problem constants ----------------
#define DD 768
#define RR 16
#define TT 8
#define M_ROWS 8192
#define NOUT 2304

// ---------------- static scratch ----------------
__device__ __align__(16) __half g_xt[M_ROWS * DD];    // x in fp16
__device__ __align__(16) __half g_wt[NOUT * DD];      // W (+ folded dW) in fp16
__device__ float g_normsq[32];                        // [Aq(8),Bq(8),Av(8),Bv(8)]

// ---------------- helpers ----------------
__device__ __forceinline__ void cp16(void* sdst, const void* gsrc) {
    unsigned s = (unsigned)__cvta_generic_to_shared(sdst);
    asm volatile("cp.async.cg.shared.global [%0], [%1], 16;\n" :: "r"(s), "l"(gsrc));
}

__device__ __forceinline__ void ldm_x4(uint32_t& d0, uint32_t& d1, uint32_t& d2,
                                       uint32_t& d3, uint32_t saddr) {
    asm volatile("ldmatrix.sync.aligned.m8n8.x4.shared.b16 {%0,%1,%2,%3}, [%4];"
                 : "=r"(d0), "=r"(d1), "=r"(d2), "=r"(d3) : "r"(saddr));
}

__device__ __forceinline__ void mma_fp16(float c[4], const uint32_t a[4], const uint32_t b[2]) {
    asm volatile(
        "mma.sync.aligned.m16n8k16.row.col.f32.f16.f16.f32 "
        "{%0,%1,%2,%3},{%4,%5,%6,%7},{%8,%9},{%0,%1,%2,%3};\n"
        : "+f"(c[0]), "+f"(c[1]), "+f"(c[2]), "+f"(c[3])
        : "r"(a[0]), "r"(a[1]), "r"(a[2]), "r"(a[3]),
          "r"(b[0]), "r"(b[1]));
}

// ---------------- kernel 1: norms only ----------------
__global__ void norms_kernel(const float* __restrict__ Aq, const float* __restrict__ Bq,
                             const float* __restrict__ Av, const float* __restrict__ Bv) {
    __shared__ float red[1024];
    int b = blockIdx.x, which = b >> 3, t = b & 7;
    const float* p = (which == 0) ? Aq : (which == 1) ? Bq : (which == 2) ? Av : Bv;
    p += t * (RR * DD);
    float s = 0.f;
    for (int i = threadIdx.x; i < RR * DD; i += 1024) { float v = p[i]; s += v * v; }
    red[threadIdx.x] = s;
    __syncthreads();
    for (int o = 512; o > 0; o >>= 1) {
        if (threadIdx.x < o) red[threadIdx.x] += red[threadIdx.x + o];
        __syncthreads();
    }
    if (threadIdx.x == 0) g_normsq[b] = red[0];
}

// ---------------- kernel 2: merged  delta-GEMM | x-convert | w-convert ----------------
// blocks [0,72):    delta GEMM (inline-built operands), writes g_wt q/v thirds
// blocks [72,840):  x fp32->fp16 into g_xt
// blocks [840,912): qkv_w middle third fp32->fp16 into g_wt
#define DJ 192          // padded low-rank K (144 real + 48 zero)
#define DLD 200         // delta smem row pitch in halves (400 B): conflict-free ldmatrix

__device__ __forceinline__ void convert_seg(const float4* __restrict__ src,
                                            uint4* __restrict__ dst,
                                            int bid_local, int nb) {
    const int stride = nb * 256;
    int i = bid_local * 256 + threadIdx.x;
#pragma unroll
    for (int u = 0; u < 4; u++) {
        int k = i + u * stride;
        float4 a = src[2 * k], b = src[2 * k + 1];
        __half2 h0 = __floats2half2_rn(a.x, a.y);
        __half2 h1 = __floats2half2_rn(a.z, a.w);
        __half2 h2 = __floats2half2_rn(b.x, b.y);
        __half2 h3 = __floats2half2_rn(b.z, b.w);
        uint4 o;
        o.x = *reinterpret_cast<uint32_t*>(&h0);
        o.y = *reinterpret_cast<uint32_t*>(&h1);
        o.z = *reinterpret_cast<uint32_t*>(&h2);
        o.w = *reinterpret_cast<uint32_t*>(&h3);
        dst[k] = o;
    }
}

__global__ __launch_bounds__(256) void merged_kernel(
    const float4* __restrict__ x, const float4* __restrict__ wmid,
    const float* __restrict__ Aq, const float* __restrict__ laq,
    const float* __restrict__ Av, const float* __restrict__ lav,
    const float* __restrict__ Bq, const float* __restrict__ lbq,
    const float* __restrict__ Bv, const float* __restrict__ lbv,
    const float* __restrict__ gate, const float* __restrict__ alpha,
    const float* __restrict__ qkv_w) {
    int bid = blockIdx.x;
    if (bid >= 72) {
        if (bid < 840) convert_seg(x, (uint4*)g_xt, bid - 72, 768);
        else           convert_seg(wmid, (uint4*)(g_wt + (size_t)DD * DD), bid - 840, 72);
        return;
    }
    // ---- delta GEMM: dW[e,d] = sum_j Bs[e,j] * AT[d,j], folded into g_wt ----
    extern __shared__ __half smd[];
    __half* Asm = smd;              // [128][DLD]  scaled-B rows (e)
    __half* Bsm = smd + 128 * DLD;  // [128][DLD]  A^T rows (d)

    const int z = bid / 36, rem = bid - z * 36;
    const int by = rem / 6, bx = rem % 6;
    const int rowbase = by * 128, colbase = bx * 128;
    const int tid = threadIdx.x, lane = tid & 31, w = tid >> 5;
    const int g = lane >> 2, tg = lane & 3;
    const int wm = (w >> 2) * 64, wn = (w & 3) * 32;

    const float* Bsrc = z ? Bv : Bq;
    const float* lb   = z ? lbv : lbq;
    const float* Asrc = z ? Av : Aq;
    const float* la   = z ? lav : laq;

    // per-thread softmax + norm scales (identical arithmetic to old build_kernel)
    float s[TT], acur;
    {
        float mx = gate[0];
        for (int t = 1; t < TT; t++) mx = fmaxf(mx, gate[t]);
        float e[TT], se = 0.f;
        for (int t = 0; t < TT; t++) { e[t] = expf(gate[t] - mx); se += e[t]; }
        int o1 = z ? 16 : 0, o2 = z ? 24 : 8;
        for (int t = 0; t < TT; t++)
            s[t] = (e[t] / se) / (sqrtf(g_normsq[o1 + t]) * sqrtf(g_normsq[o2 + t]));
        acur = alpha[TT];
    }

    // fill Asm: 128 rows x 24 chunks of 8 halves = 3072 chunks
#pragma unroll
    for (int it = 0; it < 12; it++) {
        int v = tid + it * 256;
        int e = v / 24, j0 = (v % 24) * 8;
        float f[8];
        if (j0 < 128) {
            int t = j0 >> 4, r0 = j0 & 15;
            const float4* p = (const float4*)(Bsrc + (size_t)t * DD * RR +
                                              (size_t)(rowbase + e) * RR + r0);
            float4 u0 = p[0], u1 = p[1];
            float sc = s[t];
            f[0] = u0.x * sc; f[1] = u0.y * sc; f[2] = u0.z * sc; f[3] = u0.w * sc;
            f[4] = u1.x * sc; f[5] = u1.y * sc; f[6] = u1.z * sc; f[7] = u1.w * sc;
        } else if (j0 < 144) {
            const float4* p = (const float4*)(lb + (size_t)(rowbase + e) * RR + (j0 - 128));
            float4 u0 = p[0], u1 = p[1];
            f[0] = u0.x * acur; f[1] = u0.y * acur; f[2] = u0.z * acur; f[3] = u0.w * acur;
            f[4] = u1.x * acur; f[5] = u1.y * acur; f[6] = u1.z * acur; f[7] = u1.w * acur;
        } else {
#pragma unroll
            for (int q = 0; q < 8; q++) f[q] = 0.f;
        }
        __half2 h0 = __floats2half2_rn(f[0], f[1]);
        __half2 h1 = __floats2half2_rn(f[2], f[3]);
        __half2 h2 = __floats2half2_rn(f[4], f[5]);
        __half2 h3 = __floats2half2_rn(f[6], f[7]);
        uint4 o;
        o.x = *reinterpret_cast<uint32_t*>(&h0);
        o.y = *reinterpret_cast<uint32_t*>(&h1);
        o.z = *reinterpret_cast<uint32_t*>(&h2);
        o.w = *reinterpret_cast<uint32_t*>(&h3);
        *reinterpret_cast<uint4*>(&Asm[e * DLD + j0]) = o;
    }
    // fill Bsm (A^T gather): 8 strided scalar loads per chunk
#pragma unroll
    for (int it = 0; it < 12; it++) {
        int v = tid + it * 256;
        int dr = v / 24, j0 = (v % 24) * 8;
        int dcol = colbase + dr;
        float f[8];
#pragma unroll
        for (int q = 0; q < 8; q++) {
            int j = j0 + q;
            f[q] = (j < 128) ? Asrc[(size_t)j * DD + dcol]
                 : (j < 144) ? la[(size_t)(j - 128) * DD + dcol] : 0.f;
        }
        __half2 h0 = __floats2half2_rn(f[0], f[1]);
        __half2 h1 = __floats2half2_rn(f[2], f[3]);
        __half2 h2 = __floats2half2_rn(f[4], f[5]);
        __half2 h3 = __floats2half2_rn(f[6], f[7]);
        uint4 o;
        o.x = *reinterpret_cast<uint32_t*>(&h0);
        o.y = *reinterpret_cast<uint32_t*>(&h1);
        o.z = *reinterpret_cast<uint32_t*>(&h2);
        o.w = *reinterpret_cast<uint32_t*>(&h3);
        *reinterpret_cast<uint4*>(&Bsm[dr * DLD + j0]) = o;
    }
    __syncthreads();

    float acc[4][4][4];
#pragma unroll
    for (int i = 0; i < 4; i++)
#pragma unroll
        for (int j = 0; j < 4; j++)
#pragma unroll
            for (int k = 0; k < 4; k++) acc[i][j][k] = 0.f;

    const uint32_t a_base = (uint32_t)__cvta_generic_to_shared(Asm);
    const uint32_t b_base = (uint32_t)__cvta_generic_to_shared(Bsm);
    const int a_row = wm + (lane & 15);
    const int a_csel = (lane >> 4) << 3;
    const int b_row = wn + (lane & 7) + ((lane >> 4) << 3);
    const int b_csel = ((lane >> 3) & 1) << 3;

#pragma unroll
    for (int ks = 0; ks < DJ / 16; ks++) {
        const int kk = ks * 16;
        uint32_t afr[4][4], bfr[4][2];
#pragma unroll
        for (int fm = 0; fm < 4; fm++) {
            uint32_t addr = a_base + (uint32_t)((a_row + fm * 16) * DLD + kk + a_csel) * 2;
            ldm_x4(afr[fm][0], afr[fm][1], afr[fm][2], afr[fm][3], addr);
        }
#pragma unroll
        for (int fn2 = 0; fn2 < 2; fn2++) {
            uint32_t addr = b_base + (uint32_t)((b_row + fn2 * 16) * DLD + kk + b_csel) * 2;
            uint32_t r0, r1, r2, r3;
            ldm_x4(r0, r1, r2, r3, addr);
            bfr[fn2 * 2][0] = r0;     bfr[fn2 * 2][1] = r1;
            bfr[fn2 * 2 + 1][0] = r2; bfr[fn2 * 2 + 1][1] = r3;
        }
#pragma unroll
        for (int fm = 0; fm < 4; fm++)
#pragma unroll
            for (int fn = 0; fn < 4; fn++)
                mma_fp16(acc[fm][fn], afr[fm], bfr[fn]);
    }

    // epilogue: g_wt = fp16( qkv_w + dW )
#pragma unroll
    for (int fm = 0; fm < 4; fm++) {
        int r0 = rowbase + wm + fm * 16 + g;
        int e0 = (z ? 2 * DD : 0) + r0;
#pragma unroll
        for (int fn = 0; fn < 4; fn++) {
            int col = colbase + wn + fn * 8 + 2 * tg;
            float2 w0 = *reinterpret_cast<const float2*>(&qkv_w[(size_t)e0 * DD + col]);
            float2 w1 = *reinterpret_cast<const float2*>(&qkv_w[(size_t)(e0 + 8) * DD + col]);
            __half2 h0 = __floats2half2_rn(acc[fm][fn][0] + w0.x, acc[fm][fn][1] + w0.y);
            __half2 h1 = __floats2half2_rn(acc[fm][fn][2] + w1.x, acc[fm][fn][3] + w1.y);
            *reinterpret_cast<__half2*>(&g_wt[(size_t)e0 * DD + col]) = h0;
            *reinterpret_cast<__half2*>(&g_wt[(size_t)(e0 + 8) * DD + col]) = h1;
        }
    }
}

// ---------------- kernel 3: main GEMM (R10 measured-best config) ----------------
// Block 128x128, 8 warps 2x4, warp tile 64x32, BK=64, NS=3, 2 CTAs/SM.
#define NS 3
#define BM 128
#define BN 128
#define BK 64
#define LDSH 72

__global__ __launch_bounds__(256, 2) void gemm_main(const float* __restrict__ bias,
                                                    float* __restrict__ Cout) {
    extern __shared__ __half sm[];
    __half* As = sm;
    __half* Bs = sm + NS * BM * LDSH;

    const int tid = threadIdx.x, lane = tid & 31, w = tid >> 5;
    const int g = lane >> 2, tg = lane & 3;
    const int wm = (w >> 2) * 64, wn = (w & 3) * 32;
    const int rowbase = blockIdx.y * BM, colbase = blockIdx.x * BN;

    const __half* Ap = g_xt + (size_t)rowbase * DD;
    const __half* Bp = g_wt + (size_t)colbase * DD;
    constexpr int KT = DD / BK;  // 12

    float acc[4][4][4];
#pragma unroll
    for (int i = 0; i < 4; i++)
#pragma unroll
        for (int j = 0; j < 4; j++)
#pragma unroll
            for (int k = 0; k < 4; k++) acc[i][j][k] = 0.f;

    auto load_tile = [&](int stg, int kt) {
        int kc = kt * BK;
        __half* Ad = As + stg * (BM * LDSH);
        __half* Bd = Bs + stg * (BN * LDSH);
#pragma unroll
        for (int i = 0; i < 4; i++) {
            int v = tid + i * 256, r = v >> 3, c = (v & 7) << 3;
            cp16(Ad + r * LDSH + c, Ap + (size_t)r * DD + kc + c);
            cp16(Bd + r * LDSH + c, Bp + (size_t)r * DD + kc + c);
        }
    };

    load_tile(0, 0);
    asm volatile("cp.async.commit_group;\n" ::);
    load_tile(1, 1);
    asm volatile("cp.async.commit_group;\n" ::);

    const uint32_t a_base = (uint32_t)__cvta_generic_to_shared(As);
    const uint32_t b_base = (uint32_t)__cvta_generic_to_shared(Bs);
    const int a_row = wm + (lane & 15);
    const int a_csel = (lane >> 4) << 3;
    const int b_row = wn + (lane & 7) + ((lane >> 4) << 3);
    const int b_csel = ((lane >> 3) & 1) << 3;

    for (int kt = 0; kt < KT; kt++) {
        const int stg = kt % NS;
        if (kt == KT - 1) asm volatile("cp.async.wait_group 0;\n" ::);
        else              asm volatile("cp.async.wait_group 1;\n" ::);
        __syncthreads();
        if (kt + 2 < KT) {
            load_tile((kt + 2) % NS, kt + 2);
            asm volatile("cp.async.commit_group;\n" ::);
        }
#pragma unroll
        for (int ks = 0; ks < 4; ks++) {
            const int kk = ks * 16;
            uint32_t afr[4][4], bfr[4][2];
#pragma unroll
            for (int fm = 0; fm < 4; fm++) {
                uint32_t addr = a_base +
                    (uint32_t)(((stg * BM) + a_row + fm * 16) * LDSH + kk + a_csel) * 2;
                ldm_x4(afr[fm][0], afr[fm][1], afr[fm][2], afr[fm][3], addr);
            }
#pragma unroll
            for (int fn2 = 0; fn2 < 2; fn2++) {
                uint32_t addr = b_base +
                    (uint32_t)(((stg * BN) + b_row + fn2 * 16) * LDSH + kk + b_csel) * 2;
                uint32_t r0, r1, r2, r3;
                ldm_x4(r0, r1, r2, r3, addr);
                bfr[fn2 * 2][0] = r0;     bfr[fn2 * 2][1] = r1;
                bfr[fn2 * 2 + 1][0] = r2; bfr[fn2 * 2 + 1][1] = r3;
            }
#pragma unroll
            for (int fm = 0; fm < 4; fm++)
#pragma unroll
                for (int fn = 0; fn < 4; fn++)
                    mma_fp16(acc[fm][fn], afr[fm], bfr[fn]);
        }
    }

#pragma unroll
    for (int fm = 0; fm < 4; fm++) {
        int r0 = rowbase + wm + fm * 16 + g;
#pragma unroll
        for (int fn = 0; fn < 4; fn++) {
            int col = colbase + wn + fn * 8 + 2 * tg;
            float2 bb = *reinterpret_cast<const float2*>(bias + col);
            float2 v0 = make_float2(acc[fm][fn][0] + bb.x, acc[fm][fn][1] + bb.y);
            float2 v1 = make_float2(acc[fm][fn][2] + bb.x, acc[fm][fn][3] + bb.y);
            *reinterpret_cast<float2*>(&Cout[(size_t)r0 * NOUT + col]) = v0;
            *reinterpret_cast<float2*>(&Cout[(size_t)(r0 + 8) * NOUT + col]) = v1;
        }
    }
}

// ---------------- launch ----------------
extern "C" void kernel_launch(void* const* d_in, const int* in_sizes, int n_in,
                              void* d_out, int out_size) {
    const float* x     = (const float*)d_in[0];
    const float* qkv_w = (const float*)d_in[1];
    const float* qkv_b = (const float*)d_in[2];
    const float* la_q  = (const float*)d_in[3];
    const float* lb_q  = (const float*)d_in[4];
    const float* la_v  = (const float*)d_in[5];
    const float* lb_v  = (const float*)d_in[6];
    const float* A_q   = (const float*)d_in[7];
    const float* B_q   = (const float*)d_in[8];
    const float* A_v   = (const float*)d_in[9];
    const float* B_v   = (const float*)d_in[10];
    const float* gate  = (const float*)d_in[11];
    const float* alpha = (const float*)d_in[12];

    const int DSM  = 2 * 128 * DLD * (int)sizeof(__half);            // 102400
    const int SMEM = NS * (BM + BN) * LDSH * (int)sizeof(__half);    // 110592
    cudaFuncSetAttribute((const void*)merged_kernel,
                         cudaFuncAttributeMaxDynamicSharedMemorySize, DSM);
    cudaFuncSetAttribute((const void*)gemm_main,
                         cudaFuncAttributeMaxDynamicSharedMemorySize, SMEM);

    norms_kernel<<<32, 1024>>>(A_q, B_q, A_v, B_v);

    // delta GEMM (72) | x convert (768) | w-mid convert (72)
    merged_kernel<<<912, 256, DSM>>>((const float4*)x,
                                     (const float4*)(qkv_w + (size_t)DD * DD),
                                     A_q, la_q, A_v, la_v,
                                     B_q, lb_q, B_v, lb_v,
                                     gate, alpha, qkv_w);

    // Main GEMM: out = xt @ wt^T + bias
    gemm_main<<<dim3(18, 64), 256, SMEM>>>(qkv_b, (float*)d_out);
}